// round 16
// baseline (speedup 1.0000x reference)
#include <cuda_runtime.h>
#include <cuda_fp16.h>
#include <math.h>
#include <stdint.h>

#define N_ATOMS 16384
#define APC     64
#define N_CONF  256
#define N_MOL   64
#define DEG     32
#define EDGES   (N_ATOMS * DEG)
#define H       128
#define G       50
#define GPAD    64
#define NLAYER  6
#define TAB     8192
#define DMAX    8.66025404f

// ---------------- device scratch ----------------
__device__ __align__(16) __half g_gt[TAB * GPAD];
__device__ __align__(16) __half g_wtab[NLAYER * TAB * H];
__device__ __align__(16) uint32_t g_em[EDGES];
__device__ __align__(16) float  g_conf[N_CONF * H];
__device__ __align__(16) __half g_w1t[NLAYER * H * GPAD];
__device__ __align__(16) __half g_w2t[NLAYER * H * H];
__device__ __align__(16) __half g_cw1t[NLAYER * H * H];
__device__ __align__(16) __half g_cw2t[NLAYER * H * H];
__device__ __align__(16) __half g_iwt[NLAYER * H * H];
__device__ __align__(16) __half g_ow1t[H * H];
__device__ __align__(16) __half g_ow2t[H * H];

__device__ __forceinline__ float ssp(float x) {
    float m = fmaxf(x, 0.0f);
    return m + __logf(__expf(x - m) + __expf(-m)) - 0.69314718055994531f;
}
__device__ __forceinline__ float ssp_acc(float x) {
    float m = fmaxf(x, 0.0f);
    return m + log1pf(expf(-fabsf(x))) - 0.69314718055994531f;
}
__device__ __forceinline__ uint32_t smem_u32(const void* p) {
    uint32_t a;
    asm("{ .reg .u64 t; cvta.to.shared.u64 t, %1; cvt.u32.u64 %0, t; }" : "=r"(a) : "l"(p));
    return a;
}
__device__ __forceinline__ void ldm_x4(uint32_t& r0, uint32_t& r1, uint32_t& r2, uint32_t& r3,
                                       uint32_t a) {
    asm volatile("ldmatrix.sync.aligned.m8n8.x4.shared.b16 {%0,%1,%2,%3}, [%4];"
                 : "=r"(r0), "=r"(r1), "=r"(r2), "=r"(r3) : "r"(a));
}
__device__ __forceinline__ void ldm_x2(uint32_t& r0, uint32_t& r1, uint32_t a) {
    asm volatile("ldmatrix.sync.aligned.m8n8.x2.shared.b16 {%0,%1}, [%2];"
                 : "=r"(r0), "=r"(r1) : "r"(a));
}
__device__ __forceinline__ void mma16816(float* c, const uint32_t* a, const uint32_t* b) {
    asm volatile(
        "mma.sync.aligned.m16n8k16.row.col.f32.f16.f16.f32 "
        "{%0,%1,%2,%3}, {%4,%5,%6,%7}, {%8,%9}, {%0,%1,%2,%3};"
        : "+f"(c[0]), "+f"(c[1]), "+f"(c[2]), "+f"(c[3])
        : "r"(a[0]), "r"(a[1]), "r"(a[2]), "r"(a[3]), "r"(b[0]), "r"(b[1]));
}
__device__ __forceinline__ uint32_t h2u(float a, float b) {
    __half2 p = __floats2half2_rn(a, b);
    return *(uint32_t*)&p;
}
__device__ __forceinline__ float2 u2f2(uint32_t u) {
    __half2 h = *(__half2*)&u;
    return __half22float2(h);
}
__device__ __forceinline__ void sts32(uint32_t addr, uint32_t v) {
    asm volatile("st.shared.b32 [%0], %1;" :: "r"(addr), "r"(v));
}

// ---------------- prep: weight transposes ----------------
__device__ __forceinline__ void tr1(const float* src, __half* dst, int idx,
                                    int K, int N, int Kpad) {
    int k = idx % Kpad;
    int n = (idx / Kpad) % N;
    int l = idx / (Kpad * N);
    float v = (k < K) ? src[(size_t)l * K * N + (size_t)k * N + n] : 0.0f;
    dst[idx] = __float2half(v);
}
#define S1 (NLAYER * H * GPAD)
#define S2 (NLAYER * H * H)
#define S6 (H * H)
__global__ void prep_weights(const float* mw1, const float* mw2, const float* cw1,
                             const float* cw2, const float* iw,
                             const float* ow1, const float* ow2) {
    int idx = blockIdx.x * blockDim.x + threadIdx.x;
    if (idx < S1) { tr1(mw1, g_w1t, idx, G, H, GPAD); return; }
    idx -= S1;
    if (idx < S2) { tr1(mw2, g_w2t, idx, H, H, H); return; }
    idx -= S2;
    if (idx < S2) { tr1(cw1, g_cw1t, idx, H, H, H); return; }
    idx -= S2;
    if (idx < S2) { tr1(cw2, g_cw2t, idx, H, H, H); return; }
    idx -= S2;
    if (idx < S2) { tr1(iw, g_iwt, idx, H, H, H); return; }
    idx -= S2;
    if (idx < S6) { tr1(ow1, g_ow1t, idx, H, H, H); return; }
    idx -= S6;
    if (idx < S6) { tr1(ow2, g_ow2t, idx, H, H, H); return; }
}

__global__ void gauss_tab_kernel() {
    int k = blockIdx.x;
    int c = threadIdx.x;
    float d = (float)k * (DMAX / (float)TAB);
    const float delta = 10.0f / 49.0f;
    const float coeff = -0.5f / (delta * delta);
    float t = d - (float)c * delta;
    float v = (c < G) ? expf(coeff * t * t) : 0.0f;
    g_gt[k * GPAD + c] = __float2half(v);
}

// ---------------- table build (R13-verified: 256 knots/CTA) ----------------
#define TS_W1   0
#define TS_W2   18432
#define TS_B1   53248
#define TS_B2   53760
#define TS_TOT  54272
__global__ void __launch_bounds__(256, 2)
tab_kernel(const float* __restrict__ mb1, const float* __restrict__ mb2) {
    extern __shared__ char sm[];
    __half* sW1 = (__half*)(sm + TS_W1);
    __half* sW2 = (__half*)(sm + TS_W2);
    float* sB1 = (float*)(sm + TS_B1);
    float* sB2 = (float*)(sm + TS_B2);

    const int tid = threadIdx.x, w = tid >> 5, lane = tid & 31;
    const int g = lane >> 2, t = lane & 3;
    const int l = blockIdx.x >> 5;
    const int kb = (blockIdx.x & 31) * 256;

    {
        const uint4* w1src = (const uint4*)(g_w1t + (size_t)l * H * GPAD);
        for (int i = tid; i < 1024; i += 256) {
            int r = i >> 3, c = i & 7;
            *(uint4*)(sW1 + r * 72 + c * 8) = w1src[i];
        }
        const uint4* w2src = (const uint4*)(g_w2t + (size_t)l * H * H);
        for (int i = tid; i < 2048; i += 256) {
            int r = i >> 4, c = i & 15;
            *(uint4*)(sW2 + r * 136 + c * 8) = w2src[i];
        }
        if (tid < 128) {
            sB1[tid] = mb1[l * H + tid];
            sB2[tid] = mb2[l * H + tid];
        }
    }
    __syncthreads();

    uint32_t A1[2][4][4];
#pragma unroll
    for (int i = 0; i < 2; i++)
#pragma unroll
        for (int ks = 0; ks < 4; ks++)
#pragma unroll
            for (int r = 0; r < 4; r++) {
                int row = kb + 32 * w + 16 * i + g + 8 * (r & 1);
                int col = 16 * ks + 2 * t + 8 * (r >> 1);
                A1[i][ks][r] = *(const uint32_t*)(g_gt + (size_t)row * GPAD + col);
            }

    const int bn = lane & 7;
    const int bk = ((lane >> 3) & 1) * 8;

    uint32_t A2[2][8][4];
#pragma unroll
    for (int q = 0; q < 4; q++) {
        float C1[2][4][4];
#pragma unroll
        for (int i = 0; i < 2; i++)
#pragma unroll
            for (int n = 0; n < 4; n++)
#pragma unroll
                for (int j = 0; j < 4; j++) C1[i][n][j] = 0.0f;
#pragma unroll
        for (int ks = 0; ks < 4; ks++) {
#pragma unroll
            for (int j = 0; j < 4; j++) {
                int nt = q * 4 + j;
                uint32_t B[2];
                ldm_x2(B[0], B[1], smem_u32(sW1 + (nt * 8 + bn) * 72 + ks * 16 + bk));
                mma16816(C1[0][j], A1[0][ks], B);
                mma16816(C1[1][j], A1[1][ks], B);
            }
        }
#pragma unroll
        for (int j = 0; j < 4; j++) {
            int nt = q * 4 + j;
            int col = nt * 8 + 2 * t;
            float b0 = sB1[col], b1v = sB1[col + 1];
#pragma unroll
            for (int i = 0; i < 2; i++) {
                float u0 = ssp_acc(C1[i][j][0] + b0), u1 = ssp_acc(C1[i][j][1] + b1v);
                float u2 = ssp_acc(C1[i][j][2] + b0), u3 = ssp_acc(C1[i][j][3] + b1v);
                A2[i][nt >> 1][(nt & 1) * 2 + 0] = h2u(u0, u1);
                A2[i][nt >> 1][(nt & 1) * 2 + 1] = h2u(u2, u3);
            }
        }
    }

    float cut[2][2];
#pragma unroll
    for (int i = 0; i < 2; i++)
#pragma unroll
        for (int j = 0; j < 2; j++) {
            int rowk = kb + 32 * w + 16 * i + 8 * j + g;
            float dd = (float)rowk * (DMAX / (float)TAB);
            cut[i][j] = 0.5f * (cosf(dd * 0.31415926535f) + 1.0f);
        }

#pragma unroll
    for (int q = 0; q < 4; q++) {
        float C2[2][4][4];
#pragma unroll
        for (int i = 0; i < 2; i++)
#pragma unroll
            for (int n = 0; n < 4; n++)
#pragma unroll
                for (int j = 0; j < 4; j++) C2[i][n][j] = 0.0f;
#pragma unroll
        for (int ks = 0; ks < 8; ks++) {
#pragma unroll
            for (int j = 0; j < 4; j++) {
                int nt = q * 4 + j;
                uint32_t B[2];
                ldm_x2(B[0], B[1], smem_u32(sW2 + (nt * 8 + bn) * 136 + ks * 16 + bk));
                mma16816(C2[0][j], A2[0][ks], B);
                mma16816(C2[1][j], A2[1][ks], B);
            }
        }
#pragma unroll
        for (int j = 0; j < 4; j++) {
            int nt = q * 4 + j;
            int col = nt * 8 + 2 * t;
            float b0 = sB2[col], b1v = sB2[col + 1];
#pragma unroll
            for (int i = 0; i < 2; i++) {
                int rowk = kb + 32 * w + 16 * i + g;
                float v0 = (C2[i][j][0] + b0) * cut[i][0];
                float v1 = (C2[i][j][1] + b1v) * cut[i][0];
                float v2 = (C2[i][j][2] + b0) * cut[i][1];
                float v3 = (C2[i][j][3] + b1v) * cut[i][1];
                __half* base = g_wtab + (size_t)l * TAB * H;
                *(uint32_t*)(base + (size_t)rowk * H + col) = h2u(v0, v1);
                *(uint32_t*)(base + (size_t)(rowk + 8) * H + col) = h2u(v2, v3);
            }
        }
    }
}

// ---------------- edge metadata ----------------
__global__ void epre_kernel(const float* __restrict__ pos, const int* __restrict__ ei) {
    int e = blockIdx.x * blockDim.x + threadIdx.x;
    if (e >= EDGES) return;
    int r = ei[e], c = ei[EDGES + e];
    float dx = pos[3 * r + 0] - pos[3 * c + 0];
    float dy = pos[3 * r + 1] - pos[3 * c + 1];
    float dz = pos[3 * r + 2] - pos[3 * c + 2];
    float d = sqrtf(dx * dx + dy * dy + dz * dz);
    float x = d * ((float)TAB / DMAX);
    int idx = (int)x;
    if (idx > TAB - 2) idx = TAB - 2;
    if (idx < 0) idx = 0;
    float frac = x - (float)idx;
    int fq = (int)(frac * 8192.0f);
    if (fq > 8191) fq = 8191;
    if (fq < 0) fq = 0;
    g_em[e] = (uint32_t)idx | ((uint32_t)(r & (APC - 1)) << 13) | ((uint32_t)fq << 19);
}

// ---------------- MEGA kernel: whole network per 128-atom tile --------------
#define M_AGG  0
#define M_U    34816
#define M_W    69632
#define M_XF   104448
#define M_TOT  139264

__device__ __forceinline__ void loadw512(__half* dst, const __half* src, int tid) {
    const uint4* s = (const uint4*)src;
    for (int i = tid; i < 2048; i += 512) {
        int r = i >> 4, c = i & 15;
        *(uint4*)(dst + r * 136 + c * 8) = s[i];
    }
}
__device__ __forceinline__ void gemm8(const __half* sA, const __half* sW,
                                      int ar, int ac, int bn, int bk, int ntb,
                                      float C[8][4]) {
#pragma unroll
    for (int j = 0; j < 8; j++)
#pragma unroll
        for (int q = 0; q < 4; q++) C[j][q] = 0.0f;
#pragma unroll
    for (int ks = 0; ks < 8; ks++) {
        uint32_t A[4];
        ldm_x4(A[0], A[1], A[2], A[3], smem_u32(sA + ar * 136 + ks * 16 + ac));
#pragma unroll
        for (int j = 0; j < 8; j++) {
            uint32_t B[2];
            ldm_x2(B[0], B[1], smem_u32(sW + ((ntb + j) * 8 + bn) * 136 + ks * 16 + bk));
            mma16816(C[j], A, B);
        }
    }
}

__global__ void __launch_bounds__(512, 1)
mega_kernel(const int* __restrict__ z, const float* __restrict__ emb,
            const float* __restrict__ cb2, const float* __restrict__ ib,
            const float* __restrict__ ob1, const float* __restrict__ ob2) {
    extern __shared__ char sm[];
    __half* sAgg = (__half*)(sm + M_AGG);
    __half* sU   = (__half*)(sm + M_U);
    __half* sW   = (__half*)(sm + M_W);
    __half* sXF  = (__half*)(sm + M_XF);
    float* sRed  = (float*)(sm + M_AGG);   // overlay (readout only, zeroed first)

    const int tid = threadIdx.x, w = tid >> 5, lane = tid & 31;
    const int wp = w >> 1, wh = w & 1;
    const int g = lane >> 2, t = lane & 3;
    const int tile = blockIdx.x;
    const int ar = 16 * wp + (lane & 15);
    const int ac = (lane >> 4) << 3;
    const int bn = lane & 7;
    const int bk = ((lane >> 3) & 1) * 8;
    const int ntb = wh * 8;
    const uint32_t sUb = smem_u32(sU);
    const uint32_t sXFb = smem_u32(sXF);
    const uint32_t sAggb = smem_u32(sAgg);
    const int r0s = 16 * wp + g;

    // ---- h init (registers) + fp16 into sU ----
    float hr[8][4];
    {
        int a0 = tile * 128 + r0s;
        int z0 = z[a0] * H, z1 = z[a0 + 8] * H;
#pragma unroll
        for (int j = 0; j < 8; j++) {
            int col = (ntb + j) * 8 + 2 * t;
            hr[j][0] = emb[z0 + col];
            hr[j][1] = emb[z0 + col + 1];
            hr[j][2] = emb[z1 + col];
            hr[j][3] = emb[z1 + col + 1];
            sts32(sUb + (r0s * 136 + col) * 2, h2u(hr[j][0], hr[j][1]));
            sts32(sUb + ((r0s + 8) * 136 + col) * 2, h2u(hr[j][2], hr[j][3]));
        }
    }
    uint32_t meta[8];
#pragma unroll
    for (int i = 0; i < 8; i++)
        meta[i] = g_em[(size_t)(tile * 128 + 8 * w + i) * DEG + lane];

    loadw512(sW, g_cw1t, tid);      // cw1[0]
    __syncthreads();

    // ---- xf0 = h @ cw1[0] -> sXF ----
    {
        float C[8][4];
        gemm8(sU, sW, ar, ac, bn, bk, ntb, C);
#pragma unroll
        for (int j = 0; j < 8; j++) {
            int col = (ntb + j) * 8 + 2 * t;
            sts32(sXFb + (r0s * 136 + col) * 2, h2u(C[j][0], C[j][1]));
            sts32(sXFb + ((r0s + 8) * 136 + col) * 2, h2u(C[j][2], C[j][3]));
        }
    }
    __syncthreads();

    for (int l = 0; l < NLAYER; l++) {
        // ---- edge: table-lerp aggregate, sXF -> sAgg (sW load overlapped) ----
        loadw512(sW, g_cw2t + (size_t)l * H * H, tid);
        {
            const __half* Tl = g_wtab + (size_t)l * TAB * H;
#pragma unroll
            for (int i = 0; i < 8; i++) {
                int atom = 8 * w + i;
                int cbase = (atom & 64);
                float a0 = 0.f, a1 = 0.f, a2 = 0.f, a3 = 0.f;
#pragma unroll
                for (int e = 0; e < DEG; e++) {
                    uint32_t m = __shfl_sync(0xFFFFFFFFu, meta[i], e);
                    int idx = m & 8191;
                    int row = cbase + ((m >> 13) & 63);
                    float fr = (float)(m >> 19) * (1.0f / 8192.0f);
                    const __half* t0p = Tl + (size_t)idx * H + lane * 4;
                    uint2 q0 = *(const uint2*)t0p;
                    uint2 q1 = *(const uint2*)(t0p + H);
                    uint2 xv = *(const uint2*)(sXF + row * 136 + lane * 4);
                    float2 t0a = u2f2(q0.x), t0b = u2f2(q0.y);
                    float2 t1a = u2f2(q1.x), t1b = u2f2(q1.y);
                    float2 xa = u2f2(xv.x), xb = u2f2(xv.y);
                    float w0 = fmaf(fr, t1a.x - t0a.x, t0a.x);
                    float w1 = fmaf(fr, t1a.y - t0a.y, t0a.y);
                    float w2 = fmaf(fr, t1b.x - t0b.x, t0b.x);
                    float w3 = fmaf(fr, t1b.y - t0b.y, t0b.y);
                    a0 = fmaf(xa.x, w0, a0);
                    a1 = fmaf(xa.y, w1, a1);
                    a2 = fmaf(xb.x, w2, a2);
                    a3 = fmaf(xb.y, w3, a3);
                }
                sts32(sAggb + (atom * 136 + lane * 4) * 2, h2u(a0, a1));
                sts32(sAggb + (atom * 136 + lane * 4) * 2 + 4, h2u(a2, a3));
            }
        }
        __syncthreads();

        // ---- G1: agg @ cw2 + cb2 -> ssp -> sU ----
        {
            float C[8][4];
            gemm8(sAgg, sW, ar, ac, bn, bk, ntb, C);
#pragma unroll
            for (int j = 0; j < 8; j++) {
                int col = (ntb + j) * 8 + 2 * t;
                float b0 = __ldg(cb2 + l * H + col), b1v = __ldg(cb2 + l * H + col + 1);
                float u0 = ssp(C[j][0] + b0), u1 = ssp(C[j][1] + b1v);
                float u2 = ssp(C[j][2] + b0), u3 = ssp(C[j][3] + b1v);
                sts32(sUb + (r0s * 136 + col) * 2, h2u(u0, u1));
                sts32(sUb + ((r0s + 8) * 136 + col) * 2, h2u(u2, u3));
            }
        }
        __syncthreads();
        loadw512(sW, g_iwt + (size_t)l * H * H, tid);
        __syncthreads();

        // ---- G2: U @ iw -> h += C + ib ; hnew -> sU ----
        {
            float C[8][4];
            gemm8(sU, sW, ar, ac, bn, bk, ntb, C);
            __syncthreads();
#pragma unroll
            for (int j = 0; j < 8; j++) {
                int col = (ntb + j) * 8 + 2 * t;
                float b0 = __ldg(ib + l * H + col), b1v = __ldg(ib + l * H + col + 1);
                hr[j][0] += C[j][0] + b0;
                hr[j][1] += C[j][1] + b1v;
                hr[j][2] += C[j][2] + b0;
                hr[j][3] += C[j][3] + b1v;
                sts32(sUb + (r0s * 136 + col) * 2, h2u(hr[j][0], hr[j][1]));
                sts32(sUb + ((r0s + 8) * 136 + col) * 2, h2u(hr[j][2], hr[j][3]));
            }
        }
        if (l < NLAYER - 1) {
            loadw512(sW, g_cw1t + (size_t)(l + 1) * H * H, tid);
            __syncthreads();
            float C[8][4];
            gemm8(sU, sW, ar, ac, bn, bk, ntb, C);
#pragma unroll
            for (int j = 0; j < 8; j++) {
                int col = (ntb + j) * 8 + 2 * t;
                sts32(sXFb + (r0s * 136 + col) * 2, h2u(C[j][0], C[j][1]));
                sts32(sXFb + ((r0s + 8) * 136 + col) * 2, h2u(C[j][2], C[j][3]));
            }
            __syncthreads();
        }
    }

    // ---- readout G1' = ssp(h @ ow1 + ob1) -> sXF ; zero sRed ----
    loadw512(sW, g_ow1t, tid);
    __syncthreads();
    {
        float C[8][4];
        gemm8(sU, sW, ar, ac, bn, bk, ntb, C);
#pragma unroll
        for (int j = 0; j < 8; j++) {
            int col = (ntb + j) * 8 + 2 * t;
            float b0 = __ldg(ob1 + col), b1v = __ldg(ob1 + col + 1);
            float u0 = ssp(C[j][0] + b0), u1 = ssp(C[j][1] + b1v);
            float u2 = ssp(C[j][2] + b0), u3 = ssp(C[j][3] + b1v);
            sts32(sXFb + (r0s * 136 + col) * 2, h2u(u0, u1));
            sts32(sXFb + ((r0s + 8) * 136 + col) * 2, h2u(u2, u3));
        }
        // zero sRed (overlays sAgg; last sAgg read was layer-5 G1, barriered since)
        for (int i = tid; i < 2048; i += 512) sRed[i] = 0.0f;
    }
    __syncthreads();
    loadw512(sW, g_ow2t, tid);
    __syncthreads();
    // ---- G2': @ ow2 + ob2, per-conformer column sums ----
    {
        float C[8][4];
        gemm8(sXF, sW, ar, ac, bn, bk, ntb, C);
#pragma unroll
        for (int j = 0; j < 8; j++) {
            int col = (ntb + j) * 8 + 2 * t;
            float b0 = __ldg(ob2 + col), b1v = __ldg(ob2 + col + 1);
            float s0 = (C[j][0] + b0) + (C[j][2] + b0);
            float s1 = (C[j][1] + b1v) + (C[j][3] + b1v);
            s0 += __shfl_xor_sync(0xFFFFFFFFu, s0, 4);
            s0 += __shfl_xor_sync(0xFFFFFFFFu, s0, 8);
            s0 += __shfl_xor_sync(0xFFFFFFFFu, s0, 16);
            s1 += __shfl_xor_sync(0xFFFFFFFFu, s1, 4);
            s1 += __shfl_xor_sync(0xFFFFFFFFu, s1, 8);
            s1 += __shfl_xor_sync(0xFFFFFFFFu, s1, 16);
            if (lane < 4) {
                sRed[w * 128 + col] = s0;
                sRed[w * 128 + col + 1] = s1;
            }
        }
    }
    __syncthreads();
    for (int i = tid; i < 256; i += 512) {
        int p = i >> 7, c = i & 127;
        float v = 0.0f;
#pragma unroll
        for (int k = 0; k < 8; k++) v += sRed[(p * 8 + k) * 128 + c];
        g_conf[(size_t)(2 * tile + p) * H + c] = v;
    }
}

// ---------------- final: mol sum + head MLP ----------------
__global__ void __launch_bounds__(256, 1)
final_kernel(const float* __restrict__ hw1, const float* __restrict__ hb1,
             const float* __restrict__ hw2, const float* __restrict__ hb2,
             float* __restrict__ out) {
    extern __shared__ char sm[];
    float* s_mol = (float*)sm;
    float* s_hid = (float*)sm + 8192;
    const int tid = threadIdx.x;
    for (int idx = tid; idx < N_MOL * H; idx += 256) {
        int m = idx >> 7, c = idx & 127;
        s_mol[idx] = g_conf[(m * 4 + 0) * H + c] + g_conf[(m * 4 + 1) * H + c]
                   + g_conf[(m * 4 + 2) * H + c] + g_conf[(m * 4 + 3) * H + c];
    }
    __syncthreads();
    for (int idx = tid; idx < N_MOL * 64; idx += 256) {
        int m = idx >> 6, j = idx & 63;
        float acc = hb1[j];
#pragma unroll 4
        for (int k = 0; k < H; k++) acc += s_mol[m * H + k] * hw1[k * 64 + j];
        s_hid[idx] = ssp(acc);
    }
    __syncthreads();
    if (tid < N_MOL) {
        float acc = hb2[0];
#pragma unroll 4
        for (int j = 0; j < 64; j++) acc += s_hid[tid * 64 + j] * hw2[j];
        out[tid] = acc;
    }
}

// ---------------- launch ----------------
extern "C" void kernel_launch(void* const* d_in, const int* in_sizes, int n_in,
                              void* d_out, int out_size) {
    const int*   z   = (const int*)d_in[0];
    const float* pos = (const float*)d_in[1];
    const int*   ei  = (const int*)d_in[2];
    const float* emb = (const float*)d_in[5];
    const float* mw1 = (const float*)d_in[6];
    const float* mb1 = (const float*)d_in[7];
    const float* mw2 = (const float*)d_in[8];
    const float* mb2 = (const float*)d_in[9];
    const float* cw1 = (const float*)d_in[10];
    const float* cw2 = (const float*)d_in[11];
    const float* cb2 = (const float*)d_in[12];
    const float* iw  = (const float*)d_in[13];
    const float* ib  = (const float*)d_in[14];
    const float* ow1 = (const float*)d_in[15];
    const float* ob1 = (const float*)d_in[16];
    const float* ow2 = (const float*)d_in[17];
    const float* ob2 = (const float*)d_in[18];
    const float* hw1 = (const float*)d_in[19];
    const float* hb1 = (const float*)d_in[20];
    const float* hw2 = (const float*)d_in[21];
    const float* hb2 = (const float*)d_in[22];
    float* out = (float*)d_out;

    cudaFuncSetAttribute(tab_kernel, cudaFuncAttributeMaxDynamicSharedMemorySize, TS_TOT);
    cudaFuncSetAttribute(mega_kernel, cudaFuncAttributeMaxDynamicSharedMemorySize, M_TOT);
    cudaFuncSetAttribute(final_kernel, cudaFuncAttributeMaxDynamicSharedMemorySize, 49152);

    const int WTOT = S1 + 4 * S2 + 2 * S6;
    prep_weights<<<(WTOT + 255) / 256, 256>>>(mw1, mw2, cw1, cw2, iw, ow1, ow2);
    gauss_tab_kernel<<<TAB, 64>>>();
    tab_kernel<<<NLAYER * (TAB / 256), 256, TS_TOT>>>(mb1, mb2);
    epre_kernel<<<EDGES / 256, 256>>>(pos, ei);
    mega_kernel<<<N_ATOMS / 128, 512, M_TOT>>>(z, emb, cb2, ib, ob1, ob2);
    final_kernel<<<1, 256, 49152>>>(hw1, hb1, hw2, hb2, out);
}

// round 17
// speedup vs baseline: 1.0250x; 1.0250x over previous
#include <cuda_runtime.h>
#include <cuda_fp16.h>
#include <math.h>
#include <stdint.h>

#define N_ATOMS 16384
#define APC     64
#define N_CONF  256
#define N_MOL   64
#define DEG     32
#define EDGES   (N_ATOMS * DEG)
#define H       128
#define G       50
#define GPAD    64
#define NLAYER  6
#define TAB     8192
#define DMAX    8.66025404f

// ---------------- device scratch ----------------
__device__ __align__(16) __half g_gt[TAB * GPAD];
__device__ __align__(16) __half g_wtab[NLAYER * TAB * H];
__device__ __align__(16) uint32_t g_em[EDGES];
__device__ __align__(16) float  g_conf[N_CONF * H];
__device__ __align__(16) __half g_w1t[NLAYER * H * GPAD];
__device__ __align__(16) __half g_w2t[NLAYER * H * H];
__device__ __align__(16) __half g_cw1t[NLAYER * H * H];
__device__ __align__(16) __half g_cw2t[NLAYER * H * H];
__device__ __align__(16) __half g_iwt[NLAYER * H * H];
__device__ __align__(16) __half g_ow1t[H * H];
__device__ __align__(16) __half g_ow2t[H * H];

__device__ __forceinline__ float ssp(float x) {
    float m = fmaxf(x, 0.0f);
    return m + __logf(__expf(x - m) + __expf(-m)) - 0.69314718055994531f;
}
__device__ __forceinline__ float ssp_acc(float x) {
    float m = fmaxf(x, 0.0f);
    return m + log1pf(expf(-fabsf(x))) - 0.69314718055994531f;
}
__device__ __forceinline__ uint32_t smem_u32(const void* p) {
    uint32_t a;
    asm("{ .reg .u64 t; cvta.to.shared.u64 t, %1; cvt.u32.u64 %0, t; }" : "=r"(a) : "l"(p));
    return a;
}
__device__ __forceinline__ void ldm_x4(uint32_t& r0, uint32_t& r1, uint32_t& r2, uint32_t& r3,
                                       uint32_t a) {
    asm volatile("ldmatrix.sync.aligned.m8n8.x4.shared.b16 {%0,%1,%2,%3}, [%4];"
                 : "=r"(r0), "=r"(r1), "=r"(r2), "=r"(r3) : "r"(a));
}
__device__ __forceinline__ void ldm_x2(uint32_t& r0, uint32_t& r1, uint32_t a) {
    asm volatile("ldmatrix.sync.aligned.m8n8.x2.shared.b16 {%0,%1}, [%2];"
                 : "=r"(r0), "=r"(r1) : "r"(a));
}
__device__ __forceinline__ void mma16816(float* c, const uint32_t* a, const uint32_t* b) {
    asm volatile(
        "mma.sync.aligned.m16n8k16.row.col.f32.f16.f16.f32 "
        "{%0,%1,%2,%3}, {%4,%5,%6,%7}, {%8,%9}, {%0,%1,%2,%3};"
        : "+f"(c[0]), "+f"(c[1]), "+f"(c[2]), "+f"(c[3])
        : "r"(a[0]), "r"(a[1]), "r"(a[2]), "r"(a[3]), "r"(b[0]), "r"(b[1]));
}
__device__ __forceinline__ uint32_t h2u(float a, float b) {
    __half2 p = __floats2half2_rn(a, b);
    return *(uint32_t*)&p;
}
__device__ __forceinline__ float2 u2f2(uint32_t u) {
    __half2 h = *(__half2*)&u;
    return __half22float2(h);
}
__device__ __forceinline__ void sts32(uint32_t addr, uint32_t v) {
    asm volatile("st.shared.b32 [%0], %1;" :: "r"(addr), "r"(v));
}

// ---------------- prep: weight transposes ----------------
__device__ __forceinline__ void tr1(const float* src, __half* dst, int idx,
                                    int K, int N, int Kpad) {
    int k = idx % Kpad;
    int n = (idx / Kpad) % N;
    int l = idx / (Kpad * N);
    float v = (k < K) ? src[(size_t)l * K * N + (size_t)k * N + n] : 0.0f;
    dst[idx] = __float2half(v);
}
#define S1 (NLAYER * H * GPAD)
#define S2 (NLAYER * H * H)
#define S6 (H * H)
__global__ void prep_weights(const float* mw1, const float* mw2, const float* cw1,
                             const float* cw2, const float* iw,
                             const float* ow1, const float* ow2) {
    int idx = blockIdx.x * blockDim.x + threadIdx.x;
    if (idx < S1) { tr1(mw1, g_w1t, idx, G, H, GPAD); return; }
    idx -= S1;
    if (idx < S2) { tr1(mw2, g_w2t, idx, H, H, H); return; }
    idx -= S2;
    if (idx < S2) { tr1(cw1, g_cw1t, idx, H, H, H); return; }
    idx -= S2;
    if (idx < S2) { tr1(cw2, g_cw2t, idx, H, H, H); return; }
    idx -= S2;
    if (idx < S2) { tr1(iw, g_iwt, idx, H, H, H); return; }
    idx -= S2;
    if (idx < S6) { tr1(ow1, g_ow1t, idx, H, H, H); return; }
    idx -= S6;
    if (idx < S6) { tr1(ow2, g_ow2t, idx, H, H, H); return; }
}

__global__ void gauss_tab_kernel() {
    int k = blockIdx.x;
    int c = threadIdx.x;
    float d = (float)k * (DMAX / (float)TAB);
    const float delta = 10.0f / 49.0f;
    const float coeff = -0.5f / (delta * delta);
    float t = d - (float)c * delta;
    float v = (c < G) ? expf(coeff * t * t) : 0.0f;
    g_gt[k * GPAD + c] = __float2half(v);
}

// ---------------- table build (R13-verified: 256 knots/CTA) ----------------
#define TS_W1   0
#define TS_W2   18432
#define TS_B1   53248
#define TS_B2   53760
#define TS_TOT  54272
__global__ void __launch_bounds__(256, 2)
tab_kernel(const float* __restrict__ mb1, const float* __restrict__ mb2) {
    extern __shared__ char sm[];
    __half* sW1 = (__half*)(sm + TS_W1);
    __half* sW2 = (__half*)(sm + TS_W2);
    float* sB1 = (float*)(sm + TS_B1);
    float* sB2 = (float*)(sm + TS_B2);

    const int tid = threadIdx.x, w = tid >> 5, lane = tid & 31;
    const int g = lane >> 2, t = lane & 3;
    const int l = blockIdx.x >> 5;
    const int kb = (blockIdx.x & 31) * 256;

    {
        const uint4* w1src = (const uint4*)(g_w1t + (size_t)l * H * GPAD);
        for (int i = tid; i < 1024; i += 256) {
            int r = i >> 3, c = i & 7;
            *(uint4*)(sW1 + r * 72 + c * 8) = w1src[i];
        }
        const uint4* w2src = (const uint4*)(g_w2t + (size_t)l * H * H);
        for (int i = tid; i < 2048; i += 256) {
            int r = i >> 4, c = i & 15;
            *(uint4*)(sW2 + r * 136 + c * 8) = w2src[i];
        }
        if (tid < 128) {
            sB1[tid] = mb1[l * H + tid];
            sB2[tid] = mb2[l * H + tid];
        }
    }
    __syncthreads();

    uint32_t A1[2][4][4];
#pragma unroll
    for (int i = 0; i < 2; i++)
#pragma unroll
        for (int ks = 0; ks < 4; ks++)
#pragma unroll
            for (int r = 0; r < 4; r++) {
                int row = kb + 32 * w + 16 * i + g + 8 * (r & 1);
                int col = 16 * ks + 2 * t + 8 * (r >> 1);
                A1[i][ks][r] = *(const uint32_t*)(g_gt + (size_t)row * GPAD + col);
            }

    const int bn = lane & 7;
    const int bk = ((lane >> 3) & 1) * 8;

    uint32_t A2[2][8][4];
#pragma unroll
    for (int q = 0; q < 4; q++) {
        float C1[2][4][4];
#pragma unroll
        for (int i = 0; i < 2; i++)
#pragma unroll
            for (int n = 0; n < 4; n++)
#pragma unroll
                for (int j = 0; j < 4; j++) C1[i][n][j] = 0.0f;
#pragma unroll
        for (int ks = 0; ks < 4; ks++) {
#pragma unroll
            for (int j = 0; j < 4; j++) {
                int nt = q * 4 + j;
                uint32_t B[2];
                ldm_x2(B[0], B[1], smem_u32(sW1 + (nt * 8 + bn) * 72 + ks * 16 + bk));
                mma16816(C1[0][j], A1[0][ks], B);
                mma16816(C1[1][j], A1[1][ks], B);
            }
        }
#pragma unroll
        for (int j = 0; j < 4; j++) {
            int nt = q * 4 + j;
            int col = nt * 8 + 2 * t;
            float b0 = sB1[col], b1v = sB1[col + 1];
#pragma unroll
            for (int i = 0; i < 2; i++) {
                float u0 = ssp_acc(C1[i][j][0] + b0), u1 = ssp_acc(C1[i][j][1] + b1v);
                float u2 = ssp_acc(C1[i][j][2] + b0), u3 = ssp_acc(C1[i][j][3] + b1v);
                A2[i][nt >> 1][(nt & 1) * 2 + 0] = h2u(u0, u1);
                A2[i][nt >> 1][(nt & 1) * 2 + 1] = h2u(u2, u3);
            }
        }
    }

    float cut[2][2];
#pragma unroll
    for (int i = 0; i < 2; i++)
#pragma unroll
        for (int j = 0; j < 2; j++) {
            int rowk = kb + 32 * w + 16 * i + 8 * j + g;
            float dd = (float)rowk * (DMAX / (float)TAB);
            cut[i][j] = 0.5f * (cosf(dd * 0.31415926535f) + 1.0f);
        }

#pragma unroll
    for (int q = 0; q < 4; q++) {
        float C2[2][4][4];
#pragma unroll
        for (int i = 0; i < 2; i++)
#pragma unroll
            for (int n = 0; n < 4; n++)
#pragma unroll
                for (int j = 0; j < 4; j++) C2[i][n][j] = 0.0f;
#pragma unroll
        for (int ks = 0; ks < 8; ks++) {
#pragma unroll
            for (int j = 0; j < 4; j++) {
                int nt = q * 4 + j;
                uint32_t B[2];
                ldm_x2(B[0], B[1], smem_u32(sW2 + (nt * 8 + bn) * 136 + ks * 16 + bk));
                mma16816(C2[0][j], A2[0][ks], B);
                mma16816(C2[1][j], A2[1][ks], B);
            }
        }
#pragma unroll
        for (int j = 0; j < 4; j++) {
            int nt = q * 4 + j;
            int col = nt * 8 + 2 * t;
            float b0 = sB2[col], b1v = sB2[col + 1];
#pragma unroll
            for (int i = 0; i < 2; i++) {
                int rowk = kb + 32 * w + 16 * i + g;
                float v0 = (C2[i][j][0] + b0) * cut[i][0];
                float v1 = (C2[i][j][1] + b1v) * cut[i][0];
                float v2 = (C2[i][j][2] + b0) * cut[i][1];
                float v3 = (C2[i][j][3] + b1v) * cut[i][1];
                __half* base = g_wtab + (size_t)l * TAB * H;
                *(uint32_t*)(base + (size_t)rowk * H + col) = h2u(v0, v1);
                *(uint32_t*)(base + (size_t)(rowk + 8) * H + col) = h2u(v2, v3);
            }
        }
    }
}

// ---------------- edge metadata ----------------
__global__ void epre_kernel(const float* __restrict__ pos, const int* __restrict__ ei) {
    int e = blockIdx.x * blockDim.x + threadIdx.x;
    if (e >= EDGES) return;
    int r = ei[e], c = ei[EDGES + e];
    float dx = pos[3 * r + 0] - pos[3 * c + 0];
    float dy = pos[3 * r + 1] - pos[3 * c + 1];
    float dz = pos[3 * r + 2] - pos[3 * c + 2];
    float d = sqrtf(dx * dx + dy * dy + dz * dz);
    float x = d * ((float)TAB / DMAX);
    int idx = (int)x;
    if (idx > TAB - 2) idx = TAB - 2;
    if (idx < 0) idx = 0;
    float frac = x - (float)idx;
    int fq = (int)(frac * 8192.0f);
    if (fq > 8191) fq = 8191;
    if (fq < 0) fq = 0;
    g_em[e] = (uint32_t)idx | ((uint32_t)(r & (APC - 1)) << 13) | ((uint32_t)fq << 19);
}

// ---------------- MEGA kernel: 1 conformer (64 atoms) per CTA, 2 CTA/SM -----
// smem (bytes): sAgg 17408 | sU 17408 | sW 34816 | sXF 17408  => 87040
#define M_AGG  0
#define M_U    17408
#define M_W    34816
#define M_XF   69632
#define M_TOT  87040

__device__ __forceinline__ void loadw256(__half* dst, const __half* src, int tid) {
    const uint4* s = (const uint4*)src;
    for (int i = tid; i < 2048; i += 256) {
        int r = i >> 4, c = i & 15;
        *(uint4*)(dst + r * 136 + c * 8) = s[i];
    }
}
// C[j][0..3] += A(16 rows) x B(8 cols ntb+j); A tile has 64 rows
__device__ __forceinline__ void gemm8(const __half* sA, const __half* sW,
                                      int ar, int ac, int bn, int bk, int ntb,
                                      float C[8][4]) {
#pragma unroll
    for (int j = 0; j < 8; j++)
#pragma unroll
        for (int q = 0; q < 4; q++) C[j][q] = 0.0f;
#pragma unroll
    for (int ks = 0; ks < 8; ks++) {
        uint32_t A[4];
        ldm_x4(A[0], A[1], A[2], A[3], smem_u32(sA + ar * 136 + ks * 16 + ac));
#pragma unroll
        for (int j = 0; j < 8; j++) {
            uint32_t B[2];
            ldm_x2(B[0], B[1], smem_u32(sW + ((ntb + j) * 8 + bn) * 136 + ks * 16 + bk));
            mma16816(C[j], A, B);
        }
    }
}

__global__ void __launch_bounds__(256, 2)
mega_kernel(const int* __restrict__ z, const float* __restrict__ emb,
            const float* __restrict__ cb2, const float* __restrict__ ib,
            const float* __restrict__ ob1, const float* __restrict__ ob2) {
    extern __shared__ char sm[];
    __half* sAgg = (__half*)(sm + M_AGG);
    __half* sU   = (__half*)(sm + M_U);
    __half* sW   = (__half*)(sm + M_W);
    __half* sXF  = (__half*)(sm + M_XF);
    float* sRed  = (float*)(sm + M_AGG);   // overlay (readout only, zeroed first)

    const int tid = threadIdx.x, w = tid >> 5, lane = tid & 31;
    const int wp = w >> 1, wh = w & 1;     // wp 0..3: rows 16wp..16wp+15; wh: N-half
    const int g = lane >> 2, t = lane & 3;
    const int conf = blockIdx.x;           // one conformer (64 atoms)
    const int ar = 16 * wp + (lane & 15);
    const int ac = (lane >> 4) << 3;
    const int bn = lane & 7;
    const int bk = ((lane >> 3) & 1) * 8;
    const int ntb = wh * 8;
    const uint32_t sUb = smem_u32(sU);
    const uint32_t sXFb = smem_u32(sXF);
    const uint32_t sAggb = smem_u32(sAgg);
    const int r0s = 16 * wp + g;           // 0..15+48 = 0..63

    // ---- h init (registers) + fp16 into sU ----
    float hr[8][4];
    {
        int a0 = conf * APC + r0s;
        int z0 = z[a0] * H, z1 = z[a0 + 8] * H;
#pragma unroll
        for (int j = 0; j < 8; j++) {
            int col = (ntb + j) * 8 + 2 * t;
            hr[j][0] = emb[z0 + col];
            hr[j][1] = emb[z0 + col + 1];
            hr[j][2] = emb[z1 + col];
            hr[j][3] = emb[z1 + col + 1];
            sts32(sUb + (r0s * 136 + col) * 2, h2u(hr[j][0], hr[j][1]));
            sts32(sUb + ((r0s + 8) * 136 + col) * 2, h2u(hr[j][2], hr[j][3]));
        }
    }
    // edge metadata: warp w owns atoms 8w..8w+7 (local), lane = edge index
    uint32_t meta[8];
#pragma unroll
    for (int i = 0; i < 8; i++)
        meta[i] = g_em[(size_t)(conf * APC + 8 * w + i) * DEG + lane];

    loadw256(sW, g_cw1t, tid);      // cw1[0]
    __syncthreads();

    // ---- xf0 = h @ cw1[0] -> sXF ----
    {
        float C[8][4];
        gemm8(sU, sW, ar, ac, bn, bk, ntb, C);
#pragma unroll
        for (int j = 0; j < 8; j++) {
            int col = (ntb + j) * 8 + 2 * t;
            sts32(sXFb + (r0s * 136 + col) * 2, h2u(C[j][0], C[j][1]));
            sts32(sXFb + ((r0s + 8) * 136 + col) * 2, h2u(C[j][2], C[j][3]));
        }
    }
    __syncthreads();

    for (int l = 0; l < NLAYER; l++) {
        // ---- edge: table-lerp aggregate, sXF -> sAgg (sW load overlapped) ----
        loadw256(sW, g_cw2t + (size_t)l * H * H, tid);
        {
            const __half* Tl = g_wtab + (size_t)l * TAB * H;
#pragma unroll
            for (int i = 0; i < 8; i++) {
                int atom = 8 * w + i;      // local 0..63
                float a0 = 0.f, a1 = 0.f, a2 = 0.f, a3 = 0.f;
#pragma unroll
                for (int e = 0; e < DEG; e++) {
                    uint32_t m = __shfl_sync(0xFFFFFFFFu, meta[i], e);
                    int idx = m & 8191;
                    int row = (m >> 13) & 63;
                    float fr = (float)(m >> 19) * (1.0f / 8192.0f);
                    const __half* t0p = Tl + (size_t)idx * H + lane * 4;
                    uint2 q0 = *(const uint2*)t0p;
                    uint2 q1 = *(const uint2*)(t0p + H);
                    uint2 xv = *(const uint2*)(sXF + row * 136 + lane * 4);
                    float2 t0a = u2f2(q0.x), t0b = u2f2(q0.y);
                    float2 t1a = u2f2(q1.x), t1b = u2f2(q1.y);
                    float2 xa = u2f2(xv.x), xb = u2f2(xv.y);
                    float w0 = fmaf(fr, t1a.x - t0a.x, t0a.x);
                    float w1 = fmaf(fr, t1a.y - t0a.y, t0a.y);
                    float w2 = fmaf(fr, t1b.x - t0b.x, t0b.x);
                    float w3 = fmaf(fr, t1b.y - t0b.y, t0b.y);
                    a0 = fmaf(xa.x, w0, a0);
                    a1 = fmaf(xa.y, w1, a1);
                    a2 = fmaf(xb.x, w2, a2);
                    a3 = fmaf(xb.y, w3, a3);
                }
                sts32(sAggb + (atom * 136 + lane * 4) * 2, h2u(a0, a1));
                sts32(sAggb + (atom * 136 + lane * 4) * 2 + 4, h2u(a2, a3));
            }
        }
        __syncthreads();

        // ---- G1: agg @ cw2 + cb2 -> ssp -> sU ----
        {
            float C[8][4];
            gemm8(sAgg, sW, ar, ac, bn, bk, ntb, C);
#pragma unroll
            for (int j = 0; j < 8; j++) {
                int col = (ntb + j) * 8 + 2 * t;
                float b0 = __ldg(cb2 + l * H + col), b1v = __ldg(cb2 + l * H + col + 1);
                float u0 = ssp(C[j][0] + b0), u1 = ssp(C[j][1] + b1v);
                float u2 = ssp(C[j][2] + b0), u3 = ssp(C[j][3] + b1v);
                sts32(sUb + (r0s * 136 + col) * 2, h2u(u0, u1));
                sts32(sUb + ((r0s + 8) * 136 + col) * 2, h2u(u2, u3));
            }
        }
        __syncthreads();
        loadw256(sW, g_iwt + (size_t)l * H * H, tid);
        __syncthreads();

        // ---- G2: U @ iw -> h += C + ib ; hnew -> sU ----
        {
            float C[8][4];
            gemm8(sU, sW, ar, ac, bn, bk, ntb, C);
            __syncthreads();
#pragma unroll
            for (int j = 0; j < 8; j++) {
                int col = (ntb + j) * 8 + 2 * t;
                float b0 = __ldg(ib + l * H + col), b1v = __ldg(ib + l * H + col + 1);
                hr[j][0] += C[j][0] + b0;
                hr[j][1] += C[j][1] + b1v;
                hr[j][2] += C[j][2] + b0;
                hr[j][3] += C[j][3] + b1v;
                sts32(sUb + (r0s * 136 + col) * 2, h2u(hr[j][0], hr[j][1]));
                sts32(sUb + ((r0s + 8) * 136 + col) * 2, h2u(hr[j][2], hr[j][3]));
            }
        }
        if (l < NLAYER - 1) {
            loadw256(sW, g_cw1t + (size_t)(l + 1) * H * H, tid);
            __syncthreads();
            float C[8][4];
            gemm8(sU, sW, ar, ac, bn, bk, ntb, C);
#pragma unroll
            for (int j = 0; j < 8; j++) {
                int col = (ntb + j) * 8 + 2 * t;
                sts32(sXFb + (r0s * 136 + col) * 2, h2u(C[j][0], C[j][1]));
                sts32(sXFb + ((r0s + 8) * 136 + col) * 2, h2u(C[j][2], C[j][3]));
            }
            __syncthreads();
        }
    }

    // ---- readout G1' = ssp(h @ ow1 + ob1) -> sXF ; zero sRed ----
    loadw256(sW, g_ow1t, tid);
    __syncthreads();
    {
        float C[8][4];
        gemm8(sU, sW, ar, ac, bn, bk, ntb, C);
#pragma unroll
        for (int j = 0; j < 8; j++) {
            int col = (ntb + j) * 8 + 2 * t;
            float b0 = __ldg(ob1 + col), b1v = __ldg(ob1 + col + 1);
            float u0 = ssp(C[j][0] + b0), u1 = ssp(C[j][1] + b1v);
            float u2 = ssp(C[j][2] + b0), u3 = ssp(C[j][3] + b1v);
            sts32(sXFb + (r0s * 136 + col) * 2, h2u(u0, u1));
            sts32(sXFb + ((r0s + 8) * 136 + col) * 2, h2u(u2, u3));
        }
        for (int i = tid; i < 1024; i += 256) sRed[i] = 0.0f;  // 8 warps x 128 cols
    }
    __syncthreads();
    loadw256(sW, g_ow2t, tid);
    __syncthreads();
    // ---- G2': @ ow2 + ob2, column sums over all 64 rows ----
    {
        float C[8][4];
        gemm8(sXF, sW, ar, ac, bn, bk, ntb, C);
#pragma unroll
        for (int j = 0; j < 8; j++) {
            int col = (ntb + j) * 8 + 2 * t;
            float b0 = __ldg(ob2 + col), b1v = __ldg(ob2 + col + 1);
            float s0 = (C[j][0] + b0) + (C[j][2] + b0);
            float s1 = (C[j][1] + b1v) + (C[j][3] + b1v);
            s0 += __shfl_xor_sync(0xFFFFFFFFu, s0, 4);
            s0 += __shfl_xor_sync(0xFFFFFFFFu, s0, 8);
            s0 += __shfl_xor_sync(0xFFFFFFFFu, s0, 16);
            s1 += __shfl_xor_sync(0xFFFFFFFFu, s1, 4);
            s1 += __shfl_xor_sync(0xFFFFFFFFu, s1, 8);
            s1 += __shfl_xor_sync(0xFFFFFFFFu, s1, 16);
            if (lane < 4) {
                sRed[w * 128 + col] = s0;
                sRed[w * 128 + col + 1] = s1;
            }
        }
    }
    __syncthreads();
    for (int c = tid; c < H; c += 256) {
        float v = 0.0f;
#pragma unroll
        for (int k = 0; k < 8; k++) v += sRed[k * 128 + c];
        g_conf[(size_t)conf * H + c] = v;
    }
}

// ---------------- final: mol sum + head MLP ----------------
__global__ void __launch_bounds__(256, 1)
final_kernel(const float* __restrict__ hw1, const float* __restrict__ hb1,
             const float* __restrict__ hw2, const float* __restrict__ hb2,
             float* __restrict__ out) {
    extern __shared__ char sm[];
    float* s_mol = (float*)sm;
    float* s_hid = (float*)sm + 8192;
    const int tid = threadIdx.x;
    for (int idx = tid; idx < N_MOL * H; idx += 256) {
        int m = idx >> 7, c = idx & 127;
        s_mol[idx] = g_conf[(m * 4 + 0) * H + c] + g_conf[(m * 4 + 1) * H + c]
                   + g_conf[(m * 4 + 2) * H + c] + g_conf[(m * 4 + 3) * H + c];
    }
    __syncthreads();
    for (int idx = tid; idx < N_MOL * 64; idx += 256) {
        int m = idx >> 6, j = idx & 63;
        float acc = hb1[j];
#pragma unroll 4
        for (int k = 0; k < H; k++) acc += s_mol[m * H + k] * hw1[k * 64 + j];
        s_hid[idx] = ssp(acc);
    }
    __syncthreads();
    if (tid < N_MOL) {
        float acc = hb2[0];
#pragma unroll 4
        for (int j = 0; j < 64; j++) acc += s_hid[tid * 64 + j] * hw2[j];
        out[tid] = acc;
    }
}

// ---------------- launch ----------------
extern "C" void kernel_launch(void* const* d_in, const int* in_sizes, int n_in,
                              void* d_out, int out_size) {
    const int*   z   = (const int*)d_in[0];
    const float* pos = (const float*)d_in[1];
    const int*   ei  = (const int*)d_in[2];
    const float* emb = (const float*)d_in[5];
    const float* mw1 = (const float*)d_in[6];
    const float* mb1 = (const float*)d_in[7];
    const float* mw2 = (const float*)d_in[8];
    const float* mb2 = (const float*)d_in[9];
    const float* cw1 = (const float*)d_in[10];
    const float* cw2 = (const float*)d_in[11];
    const float* cb2 = (const float*)d_in[12];
    const float* iw  = (const float*)d_in[13];
    const float* ib  = (const float*)d_in[14];
    const float* ow1 = (const float*)d_in[15];
    const float* ob1 = (const float*)d_in[16];
    const float* ow2 = (const float*)d_in[17];
    const float* ob2 = (const float*)d_in[18];
    const float* hw1 = (const float*)d_in[19];
    const float* hb1 = (const float*)d_in[20];
    const float* hw2 = (const float*)d_in[21];
    const float* hb2 = (const float*)d_in[22];
    float* out = (float*)d_out;

    cudaFuncSetAttribute(tab_kernel, cudaFuncAttributeMaxDynamicSharedMemorySize, TS_TOT);
    cudaFuncSetAttribute(mega_kernel, cudaFuncAttributeMaxDynamicSharedMemorySize, M_TOT);
    cudaFuncSetAttribute(final_kernel, cudaFuncAttributeMaxDynamicSharedMemorySize, 49152);

    const int WTOT = S1 + 4 * S2 + 2 * S6;
    prep_weights<<<(WTOT + 255) / 256, 256>>>(mw1, mw2, cw1, cw2, iw, ow1, ow2);
    gauss_tab_kernel<<<TAB, 64>>>();
    tab_kernel<<<NLAYER * (TAB / 256), 256, TS_TOT>>>(mb1, mb2);
    epre_kernel<<<EDGES / 256, 256>>>(pos, ei);
    mega_kernel<<<N_CONF, 256, M_TOT>>>(z, emb, cb2, ib, ob1, ob2);
    final_kernel<<<1, 256, 49152>>>(hw1, hb1, hw2, hb2, out);
}